// round 7
// baseline (speedup 1.0000x reference)
#include <cuda_runtime.h>
#include <cuda_fp16.h>
#include <cstdint>

// Problem dims
#define KTOT 8192
#define MPAD 2048
#define NPAD 2048
#define MOUT 2000
#define NOUT 2000

// GEMM tiling
#define BM 128
#define BN 256
#define BK 64
#define STAGES 4
#define CHUNKS 128
#define TILES_M (MPAD / BM)         // 16
#define TILES_N (NPAD / BN)         // 8
#define NTILES (TILES_M * TILES_N)  // 128
#define TOTALG (NTILES * CHUNKS)    // 16384
#define NSM 148

#define A_STAGE_BYTES (BM * BK * 2)
#define B_STAGE_BYTES (BN * BK * 2)
#define STAGE_BYTES (A_STAGE_BYTES + B_STAGE_BYTES)
#define SMEM_TOTAL (STAGES * STAGE_BYTES)   // 192 KB

__device__ __half g_Wh[(size_t)MPAD * KTOT];
__device__ __half g_XT[(size_t)NPAD * KTOT];

// ---------------- PTX helpers ----------------
__device__ __forceinline__ uint32_t smem_u32(const void* p) {
    uint32_t a;
    asm("{ .reg .u64 t; cvta.to.shared.u64 t, %1; cvt.u32.u64 %0, t; }" : "=r"(a) : "l"(p));
    return a;
}

__device__ __forceinline__ void cp16(uint32_t s, const void* g) {
    asm volatile("cp.async.cg.shared.global [%0], [%1], 16;" :: "r"(s), "l"(g));
}

__device__ __forceinline__ void cp_commit() {
    asm volatile("cp.async.commit_group;" ::: "memory");
}

template <int N>
__device__ __forceinline__ void cp_wait() {
    asm volatile("cp.async.wait_group %0;" :: "n"(N) : "memory");
}

__device__ __forceinline__ void ldsm_x4(uint32_t* r, uint32_t addr) {
    asm volatile("ldmatrix.sync.aligned.m8n8.x4.shared.b16 {%0,%1,%2,%3}, [%4];"
                 : "=r"(r[0]), "=r"(r[1]), "=r"(r[2]), "=r"(r[3]) : "r"(addr));
}

__device__ __forceinline__ void mma16816(float* c, const uint32_t* a, const uint32_t* b) {
    asm volatile(
        "mma.sync.aligned.m16n8k16.row.col.f32.f16.f16.f32 "
        "{%0,%1,%2,%3}, {%4,%5,%6,%7}, {%8,%9}, {%0,%1,%2,%3};"
        : "+f"(c[0]), "+f"(c[1]), "+f"(c[2]), "+f"(c[3])
        : "r"(a[0]), "r"(a[1]), "r"(a[2]), "r"(a[3]), "r"(b[0]), "r"(b[1]));
}

// ---------------- Init: out[m][n] = bias[n] ----------------
__global__ void __launch_bounds__(512) init_out_kernel(const float* __restrict__ bias,
                                                       float* __restrict__ out) {
    int n = blockIdx.x * blockDim.x + threadIdx.x;
    int m = blockIdx.y;
    if (n < NOUT) out[(size_t)m * NOUT + n] = bias[n];
}

// ---------------- Conversion kernels ----------------
__global__ void __launch_bounds__(256) convert_w_kernel(const float* __restrict__ W) {
    size_t t = (size_t)blockIdx.x * blockDim.x + threadIdx.x;
    size_t idx4 = t * 4;
    if (idx4 >= (size_t)MPAD * KTOT) return;
    int row = (int)(idx4 >> 13);
    __half2* ph = reinterpret_cast<__half2*>(&g_Wh[idx4]);
    if (row < MOUT) {
        float4 v = *reinterpret_cast<const float4*>(W + idx4);
        ph[0] = __halves2half2(__float2half_rn(v.x), __float2half_rn(v.y));
        ph[1] = __halves2half2(__float2half_rn(v.z), __float2half_rn(v.w));
    } else {
        __half2 z = __float2half2_rn(0.0f);
        ph[0] = z; ph[1] = z;
    }
}

__global__ void convert_x_kernel(const float* __restrict__ X) {
    __shared__ float tile[32][33];
    int kb = blockIdx.x * 32;
    int nb = blockIdx.y * 32;
    int tx = threadIdx.x, ty = threadIdx.y;
#pragma unroll
    for (int r = 0; r < 32; r += 8) {
        int k = kb + ty + r;
        int n = nb + tx;
        tile[ty + r][tx] = (n < NOUT) ? X[(size_t)k * NOUT + n] : 0.0f;
    }
    __syncthreads();
#pragma unroll
    for (int r = 0; r < 32; r += 8) {
        int n = nb + ty + r;
        int k = kb + tx;
        g_XT[(size_t)n * KTOT + k] = __float2half_rn(tile[tx][ty + r]);
    }
}

// ---------------- Persistent GEMM kernel (segmented, reg-pipelined) ------
__global__ void __launch_bounds__(256, 1)
gemm_persist_kernel(float* __restrict__ out) {
    extern __shared__ char sm[];
    const uint32_t sb = smem_u32(sm);
    const int tid = threadIdx.x;
    const int lane = tid & 31;
    const int wid = tid >> 5;
    const int warp_m = wid & 1;
    const int warp_n = wid >> 1;

    const int g0 = (int)(((long long)blockIdx.x * TOTALG) / NSM);
    const int g1 = (int)(((long long)(blockIdx.x + 1) * TOTALG) / NSM);

    // --- load addressing ---
    const int lrow = tid >> 3;
    const int lcol = tid & 7;
    uint32_t a_st[4], b_st[8];
#pragma unroll
    for (int j = 0; j < 4; j++) {
        uint32_t off = (uint32_t)((lrow + 32 * j) * 128 + lcol * 16);
        a_st[j] = off ^ ((off >> 3) & 0x70);
    }
#pragma unroll
    for (int j = 0; j < 8; j++) {
        uint32_t off = (uint32_t)((lrow + 32 * j) * 128 + lcol * 16);
        b_st[j] = off ^ ((off >> 3) & 0x70);
    }

    auto issue_loads = [&](int g, int s) {
        const int t = g >> 7;
        const int c = g & 127;
        const __half* Ab = g_Wh + ((size_t)(t >> 3) << 7) * KTOT + (size_t)c * 64 + lcol * 8;
        const __half* Bb = g_XT + ((size_t)(t & 7) << 8) * KTOT + (size_t)c * 64 + lcol * 8;
        uint32_t sA = sb + (uint32_t)s * STAGE_BYTES;
        uint32_t sB = sA + A_STAGE_BYTES;
#pragma unroll
        for (int j = 0; j < 4; j++)
            cp16(sA + a_st[j], Ab + (size_t)(lrow + 32 * j) * KTOT);
#pragma unroll
        for (int j = 0; j < 8; j++)
            cp16(sB + b_st[j], Bb + (size_t)(lrow + 32 * j) * KTOT);
    };

    // --- prologue ---
#pragma unroll
    for (int p = 0; p < STAGES - 1; p++) {
        issue_loads(g0 + p, p);
        cp_commit();
    }

    // --- compute addressing ---
    const int fr = lane & 15;
    const int kh = lane >> 4;
    const uint32_t aRow = (uint32_t)((warp_m * 64 + fr) * 128);
    const uint32_t bRow = (uint32_t)((warp_n * 64 + fr) * 128);
    const uint32_t sXor = (uint32_t)((fr & 7) << 4);
    const uint32_t kSel = (uint32_t)(kh * 16);

    const int mw0 = warp_m * 64 + (lane >> 2);
    const int nw0 = warp_n * 64 + (lane & 3) * 2;

    float acc[4][8][4];
    // double-buffered fragments
    uint32_t af[2][4][4];
    uint32_t bn[2][8][2];

    auto load_frags = [&](int buf, uint32_t aBase, uint32_t bBase, int ks) {
        const uint32_t kc = ((uint32_t)(ks * 32) + kSel) ^ sXor;
#pragma unroll
        for (int f = 0; f < 4; f++)
            ldsm_x4(af[buf][f], aBase + (uint32_t)(f * 2048) + kc);
#pragma unroll
        for (int t = 0; t < 4; t++) {
            uint32_t r[4];
            ldsm_x4(r, bBase + (uint32_t)(t * 2048) + kc);
            bn[buf][2 * t][0] = r[0];
            bn[buf][2 * t + 1][0] = r[1];
            bn[buf][2 * t][1] = r[2];
            bn[buf][2 * t + 1][1] = r[3];
        }
    };

    int g = g0;
    while (g < g1) {
        const int segEnd = min(g1, ((g >> 7) + 1) << 7);
        const int segTile = g >> 7;

#pragma unroll
        for (int f = 0; f < 4; f++)
#pragma unroll
            for (int j = 0; j < 8; j++)
#pragma unroll
                for (int e = 0; e < 4; e++) acc[f][j][e] = 0.0f;

#pragma unroll 1
        for (; g < segEnd; g++) {
            cp_wait<STAGES - 2>();
            __syncthreads();

            const int pg = g + STAGES - 1;
            if (pg < g1) issue_loads(pg, (pg - g0) & (STAGES - 1));
            cp_commit();

            const uint32_t sA = sb + (uint32_t)((g - g0) & (STAGES - 1)) * STAGE_BYTES;
            const uint32_t sB = sA + A_STAGE_BYTES;
            const uint32_t aBase = sA + aRow;
            const uint32_t bBase = sB + bRow;

            // register-pipelined ks loop: load ks+1 before MMAs of ks
            load_frags(0, aBase, bBase, 0);
#pragma unroll
            for (int ks = 0; ks < 4; ks++) {
                const int cur = ks & 1;
                if (ks < 3) load_frags(cur ^ 1, aBase, bBase, ks + 1);
#pragma unroll
                for (int f = 0; f < 4; f++)
#pragma unroll
                    for (int j = 0; j < 8; j++)
                        mma16816(acc[f][j], af[cur][f], bn[cur][j]);
            }
        }

        // --- segment epilogue: RED-add partial tile ---
        {
            const int m0 = (segTile >> 3) << 7;
            const int n0 = (segTile & 7) << 8;
#pragma unroll
            for (int f = 0; f < 4; f++) {
                int m_a = m0 + mw0 + f * 16;
                int m_b = m_a + 8;
#pragma unroll
                for (int j = 0; j < 8; j++) {
                    int n = n0 + nw0 + j * 8;
                    if (n < NOUT) {
                        if (m_a < MOUT) {
                            atomicAdd(out + (size_t)m_a * NOUT + n,     acc[f][j][0]);
                            atomicAdd(out + (size_t)m_a * NOUT + n + 1, acc[f][j][1]);
                        }
                        if (m_b < MOUT) {
                            atomicAdd(out + (size_t)m_b * NOUT + n,     acc[f][j][2]);
                            atomicAdd(out + (size_t)m_b * NOUT + n + 1, acc[f][j][3]);
                        }
                    }
                }
            }
        }
    }
}

// ---------------- launch ----------------
extern "C" void kernel_launch(void* const* d_in, const int* in_sizes, int n_in,
                              void* d_out, int out_size) {
    const float* W    = (const float*)d_in[0];
    const float* bias = (const float*)d_in[1];
    const float* X    = (const float*)d_in[2];
    float* out        = (float*)d_out;

    (void)in_sizes; (void)n_in; (void)out_size;

    {   // out = bias broadcast
        dim3 grid((NOUT + 511) / 512, MOUT);
        init_out_kernel<<<grid, 512>>>(bias, out);
    }
    {   // W -> fp16
        size_t quads = (size_t)MPAD * KTOT / 4;
        int blocks = (int)((quads + 255) / 256);
        convert_w_kernel<<<blocks, 256>>>(W);
    }
    {   // X transpose to fp16 K-major
        dim3 grid(KTOT / 32, NPAD / 32);
        dim3 block(32, 8);
        convert_x_kernel<<<grid, block>>>(X);
    }
    cudaFuncSetAttribute(gemm_persist_kernel,
                         cudaFuncAttributeMaxDynamicSharedMemorySize, SMEM_TOTAL);
    gemm_persist_kernel<<<NSM, 256, SMEM_TOTAL>>>(out);
}

// round 8
// speedup vs baseline: 1.0267x; 1.0267x over previous
#include <cuda_runtime.h>
#include <cuda_fp16.h>
#include <cstdint>

// Problem dims
#define KTOT 8192
#define MPAD 2048
#define NPAD 2048
#define MOUT 2000
#define NOUT 2000

// GEMM tiling: 128x128 tiles, 2 CTAs per SM
#define BM 128
#define BN 128
#define BK 64
#define STAGES 3
#define CHUNKS 128
#define TILES_M (MPAD / BM)         // 16
#define TILES_N (NPAD / BN)         // 16
#define NTILES (TILES_M * TILES_N)  // 256
#define TOTALG (NTILES * CHUNKS)    // 32768

#define A_STAGE_BYTES (BM * BK * 2)   // 16 KB
#define B_STAGE_BYTES (BN * BK * 2)   // 16 KB
#define STAGE_BYTES (A_STAGE_BYTES + B_STAGE_BYTES)  // 32 KB
#define SMEM_TOTAL (STAGES * STAGE_BYTES)            // 96 KB

__device__ __half g_Wh[(size_t)MPAD * KTOT];
__device__ __half g_XT[(size_t)NPAD * KTOT];

// ---------------- PTX helpers ----------------
__device__ __forceinline__ uint32_t smem_u32(const void* p) {
    uint32_t a;
    asm("{ .reg .u64 t; cvta.to.shared.u64 t, %1; cvt.u32.u64 %0, t; }" : "=r"(a) : "l"(p));
    return a;
}

__device__ __forceinline__ void cp16(uint32_t s, const void* g) {
    asm volatile("cp.async.cg.shared.global [%0], [%1], 16;" :: "r"(s), "l"(g));
}

__device__ __forceinline__ void cp_commit() {
    asm volatile("cp.async.commit_group;" ::: "memory");
}

template <int N>
__device__ __forceinline__ void cp_wait() {
    asm volatile("cp.async.wait_group %0;" :: "n"(N) : "memory");
}

__device__ __forceinline__ void ldsm_x4(uint32_t* r, uint32_t addr) {
    asm volatile("ldmatrix.sync.aligned.m8n8.x4.shared.b16 {%0,%1,%2,%3}, [%4];"
                 : "=r"(r[0]), "=r"(r[1]), "=r"(r[2]), "=r"(r[3]) : "r"(addr));
}

__device__ __forceinline__ void mma16816(float* c, const uint32_t* a, const uint32_t* b) {
    asm volatile(
        "mma.sync.aligned.m16n8k16.row.col.f32.f16.f16.f32 "
        "{%0,%1,%2,%3}, {%4,%5,%6,%7}, {%8,%9}, {%0,%1,%2,%3};"
        : "+f"(c[0]), "+f"(c[1]), "+f"(c[2]), "+f"(c[3])
        : "r"(a[0]), "r"(a[1]), "r"(a[2]), "r"(a[3]), "r"(b[0]), "r"(b[1]));
}

// ---------------- Init: out[m][n] = bias[n] ----------------
__global__ void __launch_bounds__(512) init_out_kernel(const float* __restrict__ bias,
                                                       float* __restrict__ out) {
    int n = blockIdx.x * blockDim.x + threadIdx.x;
    int m = blockIdx.y;
    if (n < NOUT) out[(size_t)m * NOUT + n] = bias[n];
}

// ---------------- Conversion kernels ----------------
__global__ void __launch_bounds__(256) convert_w_kernel(const float* __restrict__ W) {
    size_t t = (size_t)blockIdx.x * blockDim.x + threadIdx.x;
    size_t idx4 = t * 4;
    if (idx4 >= (size_t)MPAD * KTOT) return;
    int row = (int)(idx4 >> 13);
    __half2* ph = reinterpret_cast<__half2*>(&g_Wh[idx4]);
    if (row < MOUT) {
        float4 v = *reinterpret_cast<const float4*>(W + idx4);
        ph[0] = __halves2half2(__float2half_rn(v.x), __float2half_rn(v.y));
        ph[1] = __halves2half2(__float2half_rn(v.z), __float2half_rn(v.w));
    } else {
        __half2 z = __float2half2_rn(0.0f);
        ph[0] = z; ph[1] = z;
    }
}

__global__ void convert_x_kernel(const float* __restrict__ X) {
    __shared__ float tile[32][33];
    int kb = blockIdx.x * 32;
    int nb = blockIdx.y * 32;
    int tx = threadIdx.x, ty = threadIdx.y;
#pragma unroll
    for (int r = 0; r < 32; r += 8) {
        int k = kb + ty + r;
        int n = nb + tx;
        tile[ty + r][tx] = (n < NOUT) ? X[(size_t)k * NOUT + n] : 0.0f;
    }
    __syncthreads();
#pragma unroll
    for (int r = 0; r < 32; r += 8) {
        int n = nb + ty + r;
        int k = kb + tx;
        g_XT[(size_t)n * KTOT + k] = __float2half_rn(tile[tx][ty + r]);
    }
}

// ---------------- Persistent GEMM kernel: 2 CTAs/SM, 128x128 tiles ----------
// Work unit g in [0, TOTALG): tile t = g>>7 (tm = t&15 -> M, tn = t>>4 -> N),
// K-chunk c = g&127. CTA j covers [j*TOTALG/ncta, (j+1)*TOTALG/ncta):
// ~108-111 units, crosses <=1 tile boundary. Atomics finish partial tiles.
__global__ void __launch_bounds__(256, 2)
gemm_persist_kernel(float* __restrict__ out) {
    extern __shared__ char sm[];
    const uint32_t sb = smem_u32(sm);
    const int tid = threadIdx.x;
    const int lane = tid & 31;
    const int wid = tid >> 5;
    const int warp_m = wid & 1;     // 2 warps over M (64 rows each)
    const int warp_n = wid >> 1;    // 4 warps over N (32 cols each)

    const int ncta = gridDim.x;
    const int g0 = (int)(((long long)blockIdx.x * TOTALG) / ncta);
    const int g1 = (int)(((long long)(blockIdx.x + 1) * TOTALG) / ncta);

    // --- load addressing: A and B tiles have identical geometry (128x128B) ---
    const int lrow = tid >> 3;      // 0..31
    const int lcol = tid & 7;
    uint32_t st_off[4];
#pragma unroll
    for (int j = 0; j < 4; j++) {
        uint32_t off = (uint32_t)((lrow + 32 * j) * 128 + lcol * 16);
        st_off[j] = off ^ ((off >> 3) & 0x70);
    }

    auto issue_loads = [&](int g, int s) {
        const int t = g >> 7;
        const int c = g & 127;
        const __half* Ab = g_Wh + ((size_t)(t & 15) << 7) * KTOT + (size_t)c * 64 + lcol * 8;
        const __half* Bb = g_XT + ((size_t)(t >> 4) << 7) * KTOT + (size_t)c * 64 + lcol * 8;
        uint32_t sA = sb + (uint32_t)s * STAGE_BYTES;
        uint32_t sB = sA + A_STAGE_BYTES;
#pragma unroll
        for (int j = 0; j < 4; j++)
            cp16(sA + st_off[j], Ab + (size_t)(lrow + 32 * j) * KTOT);
#pragma unroll
        for (int j = 0; j < 4; j++)
            cp16(sB + st_off[j], Bb + (size_t)(lrow + 32 * j) * KTOT);
    };

    // --- prologue: fill 2 stages ---
    issue_loads(g0, 0);
    cp_commit();
    issue_loads(g0 + 1, 1);
    cp_commit();

    // --- compute addressing ---
    const int fr = lane & 15;
    const int kh = lane >> 4;
    const uint32_t aRow = (uint32_t)((warp_m * 64 + fr) * 128);
    const uint32_t bRow = (uint32_t)((warp_n * 32 + fr) * 128);
    const uint32_t sXor = (uint32_t)((fr & 7) << 4);
    const uint32_t kSel = (uint32_t)(kh * 16);

    const int mw0 = warp_m * 64 + (lane >> 2);
    const int nw0 = warp_n * 32 + (lane & 3) * 2;

    float acc[4][4][4];

    int g = g0;
    int cs = 0;                       // stage being consumed
    int ps = STAGES - 1;              // stage being prefetched into (2)
    while (g < g1) {
        const int segEnd = min(g1, ((g >> 7) + 1) << 7);
        const int segTile = g >> 7;

#pragma unroll
        for (int f = 0; f < 4; f++)
#pragma unroll
            for (int j = 0; j < 4; j++)
#pragma unroll
                for (int e = 0; e < 4; e++) acc[f][j][e] = 0.0f;

#pragma unroll 1
        for (; g < segEnd; g++) {
            cp_wait<STAGES - 2>();
            __syncthreads();

            const int pg = g + STAGES - 1;
            if (pg < g1) issue_loads(pg, ps);
            cp_commit();

            const uint32_t sA = sb + (uint32_t)cs * STAGE_BYTES;
            const uint32_t sB = sA + A_STAGE_BYTES;
            const uint32_t aBase = sA + aRow;
            const uint32_t bBase = sB + bRow;

#pragma unroll
            for (int ks = 0; ks < 4; ks++) {
                const uint32_t kc = ((uint32_t)(ks * 32) + kSel) ^ sXor;
                uint32_t af[4][4];
#pragma unroll
                for (int f = 0; f < 4; f++)
                    ldsm_x4(af[f], aBase + (uint32_t)(f * 2048) + kc);
                uint32_t bn[4][2];
#pragma unroll
                for (int t = 0; t < 2; t++) {
                    uint32_t r[4];
                    ldsm_x4(r, bBase + (uint32_t)(t * 2048) + kc);
                    bn[2 * t][0] = r[0];
                    bn[2 * t + 1][0] = r[1];
                    bn[2 * t][1] = r[2];
                    bn[2 * t + 1][1] = r[3];
                }
#pragma unroll
                for (int f = 0; f < 4; f++)
#pragma unroll
                    for (int j = 0; j < 4; j++)
                        mma16816(acc[f][j], af[f], bn[j]);
            }

            if (++cs == STAGES) cs = 0;
            if (++ps == STAGES) ps = 0;
        }

        // --- segment epilogue: RED-add partial tile ---
        {
            const int m0 = (segTile & 15) << 7;
            const int n0 = (segTile >> 4) << 7;
#pragma unroll
            for (int f = 0; f < 4; f++) {
                int m_a = m0 + mw0 + f * 16;
                int m_b = m_a + 8;
#pragma unroll
                for (int j = 0; j < 4; j++) {
                    int n = n0 + nw0 + j * 8;
                    if (n < NOUT) {
                        if (m_a < MOUT) {
                            atomicAdd(out + (size_t)m_a * NOUT + n,     acc[f][j][0]);
                            atomicAdd(out + (size_t)m_a * NOUT + n + 1, acc[f][j][1]);
                        }
                        if (m_b < MOUT) {
                            atomicAdd(out + (size_t)m_b * NOUT + n,     acc[f][j][2]);
                            atomicAdd(out + (size_t)m_b * NOUT + n + 1, acc[f][j][3]);
                        }
                    }
                }
            }
        }
    }
}

// ---------------- launch ----------------
extern "C" void kernel_launch(void* const* d_in, const int* in_sizes, int n_in,
                              void* d_out, int out_size) {
    const float* W    = (const float*)d_in[0];
    const float* bias = (const float*)d_in[1];
    const float* X    = (const float*)d_in[2];
    float* out        = (float*)d_out;

    (void)in_sizes; (void)n_in; (void)out_size;

    {   // out = bias broadcast
        dim3 grid((NOUT + 511) / 512, MOUT);
        init_out_kernel<<<grid, 512>>>(bias, out);
    }
    {   // W -> fp16
        size_t quads = (size_t)MPAD * KTOT / 4;
        int blocks = (int)((quads + 255) / 256);
        convert_w_kernel<<<blocks, 256>>>(W);
    }
    {   // X transpose to fp16 K-major
        dim3 grid(KTOT / 32, NPAD / 32);
        dim3 block(32, 8);
        convert_x_kernel<<<grid, block>>>(X);
    }

    int nsm = 148;
    cudaDeviceGetAttribute(&nsm, cudaDevAttrMultiProcessorCount, 0);
    cudaFuncSetAttribute(gemm_persist_kernel,
                         cudaFuncAttributeMaxDynamicSharedMemorySize, SMEM_TOTAL);
    gemm_persist_kernel<<<2 * nsm, 256, SMEM_TOTAL>>>(out);
}